// round 8
// baseline (speedup 1.0000x reference)
#include <cuda_runtime.h>
#include <cuda_bf16.h>

#define NB 4
#define NL 1024
#define ND 768
#define NH 12
#define NHD 64
#define NSCALE 0.125f

typedef __nv_bfloat16 bf16;

// global scratch (allocation-free rule)
__device__ bf16 g_Xhi[NB*NL*ND], g_Xlo[NB*NL*ND];
__device__ bf16 g_Wihi[3*ND*ND], g_Wilo[3*ND*ND];
__device__ bf16 g_Wohi[ND*ND],   g_Wolo[ND*ND];
__device__ bf16 g_Qhi[NB*NH*NL*NHD], g_Qlo[NB*NH*NL*NHD];
__device__ bf16 g_Khi[NB*NH*NL*NHD], g_Klo[NB*NH*NL*NHD];
__device__ bf16 g_Vhi[NB*NH*NL*NHD], g_Vlo[NB*NH*NL*NHD];
__device__ bf16 g_Ohi[NB*NL*ND], g_Olo[NB*NL*ND];

__device__ __forceinline__ unsigned smu(const void* p){ return (unsigned)__cvta_generic_to_shared(p); }

__device__ __forceinline__ void ldsm4(unsigned r[4], unsigned a){
    asm volatile("ldmatrix.sync.aligned.m8n8.x4.shared.b16 {%0,%1,%2,%3},[%4];"
                 :"=r"(r[0]),"=r"(r[1]),"=r"(r[2]),"=r"(r[3]):"r"(a));
}
__device__ __forceinline__ void ldsm4t(unsigned r[4], unsigned a){
    asm volatile("ldmatrix.sync.aligned.m8n8.x4.trans.shared.b16 {%0,%1,%2,%3},[%4];"
                 :"=r"(r[0]),"=r"(r[1]),"=r"(r[2]),"=r"(r[3]):"r"(a));
}
__device__ __forceinline__ void mma16816(float c[4], const unsigned a[4], unsigned b0, unsigned b1){
    asm volatile("mma.sync.aligned.m16n8k16.row.col.f32.bf16.bf16.f32 "
                 "{%0,%1,%2,%3},{%4,%5,%6,%7},{%8,%9},{%0,%1,%2,%3};"
                 :"+f"(c[0]),"+f"(c[1]),"+f"(c[2]),"+f"(c[3])
                 :"r"(a[0]),"r"(a[1]),"r"(a[2]),"r"(a[3]),"r"(b0),"r"(b1));
}
__device__ __forceinline__ void split2(float x0, float x1, unsigned& hi, unsigned& lo){
    bf16 h0 = __float2bfloat16(x0), h1 = __float2bfloat16(x1);
    bf16 l0 = __float2bfloat16(x0 - __bfloat162float(h0));
    bf16 l1 = __float2bfloat16(x1 - __bfloat162float(h1));
    hi = (unsigned)__bfloat16_as_ushort(h0) | ((unsigned)__bfloat16_as_ushort(h1) << 16);
    lo = (unsigned)__bfloat16_as_ushort(l0) | ((unsigned)__bfloat16_as_ushort(l1) << 16);
}
__device__ __forceinline__ void cpa16(unsigned d, const void* s){
    asm volatile("cp.async.cg.shared.global [%0],[%1],16;"::"r"(d),"l"(s));
}
__device__ __forceinline__ void cp_commit(){ asm volatile("cp.async.commit_group;"); }
template<int N> __device__ __forceinline__ void cp_wait(){
    asm volatile("cp.async.wait_group %0;"::"n"(N));
}

__global__ void split_inputs(const float* __restrict__ x, const float* __restrict__ wi,
                             const float* __restrict__ wo){
    const int st = gridDim.x * blockDim.x, i0 = blockIdx.x * blockDim.x + threadIdx.x;
    unsigned h0,l0,h1,l1;
    for (int i = i0; i < (NB*NL*ND)/4; i += st){
        float4 v = ((const float4*)x)[i];
        split2(v.x,v.y,h0,l0); split2(v.z,v.w,h1,l1);
        ((uint2*)g_Xhi)[i] = make_uint2(h0,h1); ((uint2*)g_Xlo)[i] = make_uint2(l0,l1);
    }
    for (int i = i0; i < (3*ND*ND)/4; i += st){
        float4 v = ((const float4*)wi)[i];
        split2(v.x,v.y,h0,l0); split2(v.z,v.w,h1,l1);
        ((uint2*)g_Wihi)[i] = make_uint2(h0,h1); ((uint2*)g_Wilo)[i] = make_uint2(l0,l1);
    }
    for (int i = i0; i < (ND*ND)/4; i += st){
        float4 v = ((const float4*)wo)[i];
        split2(v.x,v.y,h0,l0); split2(v.z,v.w,h1,l1);
        ((uint2*)g_Wohi)[i] = make_uint2(h0,h1); ((uint2*)g_Wolo)[i] = make_uint2(l0,l1);
    }
}

__device__ __forceinline__ void scatter_qkv(int m, int n, float v){
    const int b = m >> 10, l = m & 1023;
    bf16 *hi, *lo; int nn;
    if (n < ND)        { hi=g_Qhi; lo=g_Qlo; nn=n;      v *= NSCALE; }
    else if (n < 2*ND) { hi=g_Khi; lo=g_Klo; nn=n-ND;   }
    else               { hi=g_Vhi; lo=g_Vlo; nn=n-2*ND; }
    const size_t idx = (((size_t)b*NH + (nn>>6))*NL + l)*NHD + (nn&63);
    bf16 hv = __float2bfloat16(v);
    hi[idx] = hv; lo[idx] = __float2bfloat16(v - __bfloat162float(hv));
}

// GEMM C[m,n] = sum_k A[m,k] W[n,k] + bias[n]; tile 128(M)x64(N)x16(K).
// 8 warps as 4(M)x2(N), warp tile 32x32 -> 32 accum regs/thread, 3 CTAs/SM.
// 4-stage cp.async pipeline (wait_group 2). Stage = A(hi,lo) 2x6144 +
// B(hi,lo) 2x3072 = 18432 B; 4 stages = 73728 B.
template <int MODE>
__global__ __launch_bounds__(256, 3)
void gemm_mma(const float* __restrict__ bias, float* __restrict__ out){
    constexpr int K = 768, NKT = 48;
    extern __shared__ char dsm[];

    const bf16* Ahi = (MODE==0) ? g_Xhi : g_Ohi;
    const bf16* Alo = (MODE==0) ? g_Xlo : g_Olo;
    const bf16* Bhi = (MODE==0) ? g_Wihi : g_Wohi;
    const bf16* Blo = (MODE==0) ? g_Wilo : g_Wolo;

    const int tid = threadIdx.x, lane = tid & 31;
    const int g = lane >> 2, t = lane & 3;
    const int wid = tid >> 5, wm = wid & 3, wn = wid >> 2;   // 4(M) x 2(N) warps
    const int m0 = blockIdx.y * 128, n0 = blockIdx.x * 64;

    // loaders: A 128 rows x 2 chunks -> all 256 threads; B 64 rows x 2 -> tid<128
    const int lrA = tid >> 1, lhA = tid & 1;
    const int lrB = (tid >> 1) & 63, lhB = tid & 1;
    const bf16* ApH = Ahi + (size_t)(m0+lrA)*K + lhA*8;
    const bf16* ApL = Alo + (size_t)(m0+lrA)*K + lhA*8;
    const bf16* BpH = Bhi + (size_t)(n0+lrB)*K + lhB*8;
    const bf16* BpL = Blo + (size_t)(n0+lrB)*K + lhB*8;
    const unsigned soA = lrA*48 + lhA*16;
    const unsigned soB = lrB*48 + lhB*16;

    float c[2][4][4];
#pragma unroll
    for (int i=0;i<2;i++)
#pragma unroll
        for (int j=0;j<4;j++){ c[i][j][0]=c[i][j][1]=c[i][j][2]=c[i][j][3]=0.f; }

#define G_ISSUE(S,KT) do{ char* st_ = dsm + (S)*18432; const int ko_ = (KT)*16;   \
    cpa16(smu(st_)+soA,      ApH+ko_); cpa16(smu(st_+6144)+soA,  ApL+ko_);        \
    if (tid < 128){                                                               \
        cpa16(smu(st_+12288)+soB, BpH+ko_); cpa16(smu(st_+15360)+soB, BpL+ko_);   \
    }                                                                             \
    cp_commit(); }while(0)

    G_ISSUE(0,0); G_ISSUE(1,1); G_ISSUE(2,2);

    const unsigned aoff = (wm*32 + (lane&15))*48 + (lane>>4)*16;
    const unsigned boff = (wn*32 + (lane&15))*48 + (lane>>4)*16;

#pragma unroll 1
    for (int kt = 0; kt < NKT; kt++){
        cp_wait<2>();
        __syncthreads();
        char* st = dsm + (kt & 3)*18432;

        unsigned ah[2][4], al[2][4], bh[2][4], bl[2][4];
#pragma unroll
        for (int im=0; im<2; im++){
            ldsm4(ah[im], smu(st)      + aoff + im*16*48);
            ldsm4(al[im], smu(st+6144) + aoff + im*16*48);
        }
#pragma unroll
        for (int jg=0; jg<2; jg++){
            ldsm4(bh[jg], smu(st+12288) + boff + jg*16*48);
            ldsm4(bl[jg], smu(st+15360) + boff + jg*16*48);
        }

        if (kt + 3 < NKT) G_ISSUE((kt+3) & 3, kt+3); else cp_commit();

        // pass 1: hi*hi (8 independent chains)
#pragma unroll
        for (int im=0; im<2; im++)
#pragma unroll
            for (int jn=0; jn<4; jn++){
                const int jg = jn>>1, od = jn&1;
                mma16816(c[im][jn], ah[im], bh[jg][od], bh[jg][od+2]);
            }
        // pass 2: lo*hi
#pragma unroll
        for (int im=0; im<2; im++)
#pragma unroll
            for (int jn=0; jn<4; jn++){
                const int jg = jn>>1, od = jn&1;
                mma16816(c[im][jn], al[im], bh[jg][od], bh[jg][od+2]);
            }
        // pass 3: hi*lo
#pragma unroll
        for (int im=0; im<2; im++)
#pragma unroll
            for (int jn=0; jn<4; jn++){
                const int jg = jn>>1, od = jn&1;
                mma16816(c[im][jn], ah[im], bl[jg][od], bl[jg][od+2]);
            }
    }

#pragma unroll
    for (int im=0; im<2; im++)
#pragma unroll
        for (int jn=0; jn<4; jn++){
            const int n = n0 + wn*32 + jn*8 + 2*t;
            const float bv0 = bias[n], bv1 = bias[n+1];
#pragma unroll
            for (int hf=0; hf<2; hf++){
                const int m = m0 + wm*32 + im*16 + g + hf*8;
                const float v0 = c[im][jn][hf*2+0] + bv0;
                const float v1 = c[im][jn][hf*2+1] + bv1;
                if (MODE == 0){ scatter_qkv(m, n, v0); scatter_qkv(m, n+1, v1); }
                else          { *(float2*)(out + (size_t)m*ND + n) = make_float2(v0, v1); }
            }
        }
}

// cp.async a 64x64 bf16 tile with chunk^=(row&7) swizzle (128 threads x 4 x 16B)
__device__ __forceinline__ void tissue(char* dst, const bf16* src, int tid){
#pragma unroll
    for (int u=0; u<4; u++){
        const int it = tid + 128*u, row = it>>3, ck = it&7, ch = ck ^ (row&7);
        cpa16(smu(dst + row*128 + ch*16), (const char*)src + row*128 + ck*16);
    }
}

// FA2 attention (mma.sync): 64 queries x (b,h) per block, 128 threads.
__global__ __launch_bounds__(128, 3)
void attn_mma(const float* __restrict__ bias){
    extern __shared__ char dsm[];
#define KBUF(s,cc) (dsm + ((s)*2+(cc))*8192)
#define VBUF(s,cc) (dsm + 32768 + ((s)*2+(cc))*8192)

    const int tid = threadIdx.x, w = tid>>5, lane = tid&31;
    const int g = lane>>2, t = lane&3;
    const int bh = blockIdx.y, q0 = blockIdx.x*64;
    const int b = bh/NH, hh = bh - b*NH;
    const size_t head = (size_t)bh*NL*NHD;

    tissue(KBUF(1,0), g_Qhi + head + (size_t)q0*NHD, tid);
    tissue(KBUF(1,1), g_Qlo + head + (size_t)q0*NHD, tid);
    tissue(KBUF(0,0), g_Khi + head, tid);
    tissue(KBUF(0,1), g_Klo + head, tid);
    tissue(VBUF(0,0), g_Vhi + head, tid);
    tissue(VBUF(0,1), g_Vlo + head, tid);
    cp_commit();
    cp_wait<0>();
    __syncthreads();

    unsigned qh[4][4], ql[4][4];
#pragma unroll
    for (int kk=0; kk<4; kk++){
        const int row = w*16 + (lane&15);
        const int ch = (kk*2 + (lane>>4)) ^ (row&7);
        ldsm4(qh[kk], smu(KBUF(1,0) + row*128 + ch*16));
        ldsm4(ql[kk], smu(KBUF(1,1) + row*128 + ch*16));
    }
    __syncthreads();

    const float* Bg = bias + ((size_t)bh*NL + q0)*NL;
    float o[8][4];
#pragma unroll
    for (int jd=0;jd<8;jd++){ o[jd][0]=o[jd][1]=o[jd][2]=o[jd][3]=0.f; }
    float mrow[2] = {-1e30f,-1e30f}, lrow[2] = {0.f,0.f};

#pragma unroll 1
    for (int kt = 0; kt < 16; kt++){
        const int cur = kt & 1;
        if (kt+1 < 16){
            const int nx = cur ^ 1;
            const size_t off = head + (size_t)(kt+1)*64*NHD;
            tissue(KBUF(nx,0), g_Khi + off, tid);
            tissue(KBUF(nx,1), g_Klo + off, tid);
            tissue(VBUF(nx,0), g_Vhi + off, tid);
            tissue(VBUF(nx,1), g_Vlo + off, tid);
        }
        cp_commit();

        float s[8][4];
        {
            const float* bp0 = Bg + (size_t)(w*16+g)*NL + kt*64 + 2*t;
            const float* bp1 = bp0 + 8*NL;
#pragma unroll
            for (int jn=0; jn<8; jn++){
                float2 v0 = *(const float2*)(bp0 + jn*8);
                float2 v1 = *(const float2*)(bp1 + jn*8);
                s[jn][0]=v0.x; s[jn][1]=v0.y; s[jn][2]=v1.x; s[jn][3]=v1.y;
            }
        }
#pragma unroll
        for (int kk=0; kk<4; kk++){
            unsigned kh[4][4], kl[4][4];
#pragma unroll
            for (int jg=0; jg<4; jg++){
                const int row = jg*16 + (lane&15);
                const int ch = (kk*2 + (lane>>4)) ^ (row&7);
                ldsm4(kh[jg], smu(KBUF(cur,0) + row*128 + ch*16));
                ldsm4(kl[jg], smu(KBUF(cur,1) + row*128 + ch*16));
            }
#pragma unroll
            for (int jn=0; jn<8; jn++){
                const int jg = jn>>1, od = jn&1;
                mma16816(s[jn], qh[kk], kh[jg][od], kh[jg][od+2]);
                mma16816(s[jn], ql[kk], kh[jg][od], kh[jg][od+2]);
                mma16816(s[jn], qh[kk], kl[jg][od], kl[jg][od+2]);
            }
        }
#pragma unroll
        for (int r=0; r<2; r++){
            float mx = -1e30f;
#pragma unroll
            for (int jn=0; jn<8; jn++) mx = fmaxf(mx, fmaxf(s[jn][2*r], s[jn][2*r+1]));
            mx = fmaxf(mx, __shfl_xor_sync(0xffffffffu, mx, 1));
            mx = fmaxf(mx, __shfl_xor_sync(0xffffffffu, mx, 2));
            const float mnew = fmaxf(mrow[r], mx);
            const float corr = __expf(mrow[r] - mnew);
            mrow[r] = mnew;
            float ls = 0.f;
#pragma unroll
            for (int jn=0; jn<8; jn++){
                const float p0 = __expf(s[jn][2*r] - mnew);
                const float p1 = __expf(s[jn][2*r+1] - mnew);
                s[jn][2*r] = p0; s[jn][2*r+1] = p1; ls += p0 + p1;
            }
            lrow[r] = lrow[r]*corr + ls;
#pragma unroll
            for (int jd=0; jd<8; jd++){ o[jd][2*r] *= corr; o[jd][2*r+1] *= corr; }
        }
#pragma unroll
        for (int kc=0; kc<4; kc++){
            unsigned aph[4], apl[4];
            split2(s[2*kc][0],   s[2*kc][1],   aph[0], apl[0]);
            split2(s[2*kc][2],   s[2*kc][3],   aph[1], apl[1]);
            split2(s[2*kc+1][0], s[2*kc+1][1], aph[2], apl[2]);
            split2(s[2*kc+1][2], s[2*kc+1][3], aph[3], apl[3]);
#pragma unroll
            for (int dch=0; dch<4; dch++){
                unsigned vh[4], vl[4];
                const int row = kc*16 + (lane&15);
                const int ch = (dch*2 + (lane>>4)) ^ (row&7);
                ldsm4t(vh, smu(VBUF(cur,0) + row*128 + ch*16));
                ldsm4t(vl, smu(VBUF(cur,1) + row*128 + ch*16));
#pragma unroll
                for (int od=0; od<2; od++){
                    const int jd = dch*2 + od;
                    mma16816(o[jd], aph, vh[od*2], vh[od*2+1]);
                    mma16816(o[jd], apl, vh[od*2], vh[od*2+1]);
                    mma16816(o[jd], aph, vl[od*2], vl[od*2+1]);
                }
            }
        }
        cp_wait<0>();
        __syncthreads();
    }

    float inv[2];
#pragma unroll
    for (int r=0; r<2; r++){
        float l = lrow[r];
        l += __shfl_xor_sync(0xffffffffu, l, 1);
        l += __shfl_xor_sync(0xffffffffu, l, 2);
        inv[r] = 1.0f / l;
    }
#pragma unroll
    for (int jd=0; jd<8; jd++)
#pragma unroll
        for (int r=0; r<2; r++){
            const int q = q0 + w*16 + g + r*8;
            const int col = hh*64 + jd*8 + 2*t;
            const size_t idx = ((size_t)b*NL + q)*ND + col;
            unsigned hi, lo;
            split2(o[jd][2*r]*inv[r], o[jd][2*r+1]*inv[r], hi, lo);
            *(unsigned*)(g_Ohi + idx) = hi;
            *(unsigned*)(g_Olo + idx) = lo;
        }
}

extern "C" void kernel_launch(void* const* d_in, const int* in_sizes, int n_in,
                              void* d_out, int out_size){
    (void)in_sizes; (void)n_in; (void)out_size;
    const float* x     = (const float*)d_in[0];
    const float* ab    = (const float*)d_in[1];
    const float* w_in  = (const float*)d_in[2];
    const float* b_in  = (const float*)d_in[3];
    const float* w_out = (const float*)d_in[4];
    const float* b_out = (const float*)d_in[5];
    float* out = (float*)d_out;

    cudaFuncSetAttribute(gemm_mma<0>, cudaFuncAttributeMaxDynamicSharedMemorySize, 73728);
    cudaFuncSetAttribute(gemm_mma<1>, cudaFuncAttributeMaxDynamicSharedMemorySize, 73728);
    cudaFuncSetAttribute(attn_mma,    cudaFuncAttributeMaxDynamicSharedMemorySize, 65536);

    split_inputs<<<512, 256>>>(x, w_in, w_out);
    gemm_mma<0><<<dim3(36, 32), 256, 73728>>>(b_in, nullptr);
    attn_mma<<<dim3(16, 48), 128, 65536>>>(ab);
    gemm_mma<1><<<dim3(12, 32), 256, 73728>>>(b_out, out);
}